// round 15
// baseline (speedup 1.0000x reference)
#include <cuda_runtime.h>
#include <cuda_fp16.h>
#include <math.h>
#include <cstdint>

#define NN 768
#define EE 24576
#define DD 1024

// ---------------- fp16 GEMM operand scratch (all [x][1024] K-major) ----------------
__device__ __align__(128) __half g_Hs16[DD * DD];
__device__ __align__(128) __half g_Ho16[DD * DD];
__device__ __align__(128) __half g_Kt16[DD * DD];
__device__ __align__(128) __half g_MT16[4 * DD * DD];
__device__ __align__(128) __half g_T16 [4 * NN * DD];
__device__ __align__(128) __half g_Wr16[3 * DD * DD];
__device__ __align__(128) __half g_WT16[5 * DD * DD];
__device__ __align__(128) __half g_vf16[NN * DD];
__device__ __align__(128) __half g_R16 [(size_t)EE * DD];
__device__ __align__(128) __half g_ctx16[NN * DD];
// ---------------- fp32 scratch ----------------
__device__ __align__(128) float g_S1[NN * DD];
__device__ __align__(128) float g_S2[NN * DD];
__device__ __align__(128) float g_G [NN * NN];
__device__ float g_cs[DD], g_co[DD], g_c3[DD];
__device__ float g_csp[8 * DD], g_cop[8 * DD];
__device__ float g_d1[NN], g_d2[NN];
__device__ __align__(128) float g_logits[EE];
__device__ __align__(128) float g_wS[EE];
__device__ __align__(128) float g_wO[EE];
__device__ unsigned g_maxS[NN], g_maxO[NN];
__device__ float g_sumS[NN], g_sumO[NN];
__device__ int g_degS[NN], g_degO[NN], g_baseS[NN], g_baseO[NN], g_curO[NN];
__device__ int g_permO[EE];

#define STR32 20
#define STG32 (128 * STR32)
#define NSTG 4
#define SMEM16_BYTES (NSTG * 2 * STG32 * 4)  // 81920 B

// ---------------- helpers ----------------
__device__ __forceinline__ void mma16(float c[4], unsigned a0, unsigned a1, unsigned a2, unsigned a3,
                                      unsigned b0, unsigned b1) {
    asm volatile(
        "mma.sync.aligned.m16n8k16.row.col.f32.f16.f16.f32 "
        "{%0,%1,%2,%3},{%4,%5,%6,%7},{%8,%9},{%0,%1,%2,%3};"
        : "+f"(c[0]), "+f"(c[1]), "+f"(c[2]), "+f"(c[3])
        : "r"(a0), "r"(a1), "r"(a2), "r"(a3), "r"(b0), "r"(b1));
}
__device__ __forceinline__ void ldsm4(unsigned& r0, unsigned& r1, unsigned& r2, unsigned& r3, uint32_t addr) {
    asm volatile("ldmatrix.sync.aligned.m8n8.x4.shared.b16 {%0,%1,%2,%3}, [%4];"
        : "=r"(r0), "=r"(r1), "=r"(r2), "=r"(r3) : "r"(addr));
}
__device__ __forceinline__ void cpa16p(void* s, const void* g) {
    unsigned sa = (unsigned)__cvta_generic_to_shared(s);
    asm volatile("cp.async.cg.shared.global [%0], [%1], 16;" :: "r"(sa), "l"(g));
}
__device__ __forceinline__ void cpa_commit() { asm volatile("cp.async.commit_group;"); }
template<int N> __device__ __forceinline__ void cpa_wait() { asm volatile("cp.async.wait_group %0;" :: "n"(N)); }

__device__ __forceinline__ unsigned fkey(float f) {
    unsigned u = __float_as_uint(f);
    return (u & 0x80000000u) ? ~u : (u | 0x80000000u);
}
__device__ __forceinline__ float funkey(unsigned k) {
    return (k & 0x80000000u) ? __uint_as_float(k ^ 0x80000000u) : __uint_as_float(~k);
}

// ---------------- fp16 NT mainloop (ldmatrix, 4-stage, nk slabs) ----------------
__device__ __forceinline__ void run_ml16(const __half* __restrict__ A,
                                         const __half* __restrict__ B,
                                         int bm, int bn, int nk,
                                         float (&acc)[4][8][4],
                                         uint32_t* __restrict__ As,
                                         uint32_t* __restrict__ Bs) {
    int tid = threadIdx.x;
    int lane = tid & 31;
    int warp = tid >> 5;
    int wm = (warp & 1) * 64;
    int wn = (warp >> 1) * 64;

    uint32_t baseA = (uint32_t)__cvta_generic_to_shared(As);
    uint32_t baseB = (uint32_t)__cvta_generic_to_shared(Bs);

    uint32_t offA[4], offB[4];
#pragma unroll
    for (int mt = 0; mt < 4; mt++)
        offA[mt] = (uint32_t)((wm + mt * 16 + (lane & 7) + ((lane >> 3) & 1) * 8) * 80 + (lane >> 4) * 16);
#pragma unroll
    for (int p = 0; p < 4; p++)
        offB[p] = (uint32_t)((wn + p * 16 + (lane & 7) + ((lane >> 4) & 1) * 8) * 80 + ((lane >> 3) & 1) * 16);

    auto issue = [&](int s) {
        int stg = s % NSTG;
        uint32_t* as = As + stg * STG32;
        uint32_t* bs = Bs + stg * STG32;
#pragma unroll
        for (int p = 0; p < 4; p++) {
            int idx = p * 128 + tid;
            int row = idx >> 2;
            int c4 = idx & 3;
            cpa16p(as + row * STR32 + c4 * 4, A + (size_t)(bm + row) * DD + s * 32 + c4 * 8);
        }
#pragma unroll
        for (int p = 0; p < 4; p++) {
            int idx = p * 128 + tid;
            int row = idx >> 2;
            int c4 = idx & 3;
            cpa16p(bs + row * STR32 + c4 * 4, B + (size_t)(bn + row) * DD + s * 32 + c4 * 8);
        }
        cpa_commit();
    };

    issue(0);
    issue(1);
    issue(2);
    for (int kt = 0; kt < nk; kt++) {
        cpa_wait<2>();
        __syncthreads();
        uint32_t ta = baseA + (uint32_t)((kt % NSTG) * STG32 * 4);
        uint32_t tb = baseB + (uint32_t)((kt % NSTG) * STG32 * 4);
#pragma unroll
        for (int kk = 0; kk < 2; kk++) {
            unsigned af[4][4], bf[8][2];
#pragma unroll
            for (int mt = 0; mt < 4; mt++)
                ldsm4(af[mt][0], af[mt][1], af[mt][2], af[mt][3], ta + offA[mt] + kk * 32);
#pragma unroll
            for (int p = 0; p < 4; p++)
                ldsm4(bf[2 * p][0], bf[2 * p][1], bf[2 * p + 1][0], bf[2 * p + 1][1],
                      tb + offB[p] + kk * 32);
#pragma unroll
            for (int mt = 0; mt < 4; mt++)
#pragma unroll
                for (int nt = 0; nt < 8; nt++)
                    mma16(acc[mt][nt], af[mt][0], af[mt][1], af[mt][2], af[mt][3],
                          bf[nt][0], bf[nt][1]);
        }
        if (kt + 3 < nk) issue(kt + 3);
    }
}

// ---------------- generalized batched NT GEMM ----------------
struct Desc {
    const __half* A; const __half* B; const __half* A2; const __half* B2;
    const __half* CaddH;          // optional half addend [m][n]
    const float* CaddRow;         // optional broadcast row addend [n]
    float* C32; __half* C16;      // exactly one non-null
    int M; int N; int ldc; int dual;
};
struct Batch { Desc d[6]; };

__global__ __launch_bounds__(128) void gemm_multi(Batch p) {
    Desc d = p.d[blockIdx.z];
    int bm = blockIdx.y * 128;
    int bn = blockIdx.x * 128;
    if (bm >= d.M || bn >= d.N) return;

    extern __shared__ uint32_t sm16[];
    uint32_t* As = sm16;
    uint32_t* Bs = sm16 + NSTG * STG32;

    float acc[4][8][4];
#pragma unroll
    for (int a = 0; a < 4; a++)
#pragma unroll
        for (int b = 0; b < 8; b++)
#pragma unroll
            for (int c = 0; c < 4; c++) acc[a][b][c] = 0.f;

    run_ml16(d.A, d.B, bm, bn, 32, acc, As, Bs);
    if (d.dual) { __syncthreads(); run_ml16(d.A2, d.B2, bm, bn, 32, acc, As, Bs); }

    int lane = threadIdx.x & 31;
    int warp = threadIdx.x >> 5;
    int wm = (warp & 1) * 64;
    int wn = (warp >> 1) * 64;
#pragma unroll
    for (int mt = 0; mt < 4; mt++)
#pragma unroll
        for (int half_ = 0; half_ < 2; half_++) {
            int r = bm + wm + mt * 16 + (lane >> 2) + half_ * 8;
#pragma unroll
            for (int nt = 0; nt < 8; nt++) {
                int c = bn + wn + nt * 8 + (lane & 3) * 2;
                float vx = acc[mt][nt][half_ * 2 + 0];
                float vy = acc[mt][nt][half_ * 2 + 1];
                if (d.CaddH) {
                    vx += __half2float(d.CaddH[(size_t)r * d.ldc + c]);
                    vy += __half2float(d.CaddH[(size_t)r * d.ldc + c + 1]);
                }
                if (d.CaddRow) {
                    vx += d.CaddRow[c];
                    vy += d.CaddRow[c + 1];
                }
                if (d.C16) {
                    __half2 h;
                    h.x = __float2half_rn(vx);
                    h.y = __float2half_rn(vy);
                    *(__half2*)(d.C16 + (size_t)r * d.ldc + c) = h;
                } else {
                    float2 v; v.x = vx; v.y = vy;
                    *(float2*)(d.C32 + (size_t)r * d.ldc + c) = v;
                }
            }
        }
}

// ---------------- E-GEMM (fp16) with fused logit epilogue, split-K2 ----------------
__global__ __launch_bounds__(128) void gemm_logit16(const int* __restrict__ sbj,
                                                    const int* __restrict__ obj) {
    extern __shared__ uint32_t sm16[];
    uint32_t* As = sm16;
    uint32_t* Bs = sm16 + NSTG * STG32;
    int bm = blockIdx.y * 128;
    int bn = blockIdx.x * 128;
    int kz = blockIdx.z;           // 0 or 1, K halves

    float acc[4][8][4];
#pragma unroll
    for (int a = 0; a < 4; a++)
#pragma unroll
        for (int b = 0; b < 8; b++)
#pragma unroll
            for (int c = 0; c < 4; c++) acc[a][b][c] = 0.f;

    run_ml16(g_R16 + kz * 512, g_Kt16 + kz * 512, bm, bn, 16, acc, As, Bs);

    int lane = threadIdx.x & 31;
    int warp = threadIdx.x >> 5;
    int wm = (warp & 1) * 64;
    int wn = (warp >> 1) * 64;
    const float scale = 0.03125f;

#pragma unroll
    for (int mt = 0; mt < 4; mt++) {
#pragma unroll
        for (int half_ = 0; half_ < 2; half_++) {
            int r = bm + wm + mt * 16 + (lane >> 2) + half_ * 8;
            int s = sbj[r], o = obj[r];
            const __half2* Rr = (const __half2*)(g_R16 + (size_t)r * DD);
            const float* S1r = g_S1 + (size_t)s * DD;
            const float* S2r = g_S2 + (size_t)o * DD;
            float part = 0.f;
#pragma unroll
            for (int nt = 0; nt < 8; nt++) {
                int c = bn + wn + nt * 8 + (lane & 3) * 2;
                float2 Rv = __half22float2(Rr[c >> 1]);
                float sx = 0.f, sy = 0.f;
                if (kz == 1) {
                    float2 s1v = *(const float2*)(S1r + c);
                    float2 s2v = *(const float2*)(S2r + c);
                    sx = s1v.x + s2v.x;
                    sy = s1v.y + s2v.y;
                }
                part += (acc[mt][nt][half_ * 2 + 0] + sx) * Rv.x;
                part += (acc[mt][nt][half_ * 2 + 1] + sy) * Rv.y;
            }
            part += __shfl_xor_sync(0xFFFFFFFF, part, 1);
            part += __shfl_xor_sync(0xFFFFFFFF, part, 2);
            if ((lane & 3) == 0) {
                if (kz == 1 && bn == 0 && wn == 0)
                    part += g_G[(size_t)s * NN + o] + g_d1[s] + g_d2[o];
                atomicAdd(&g_logits[r], part * scale);
            }
        }
    }
}

// ---------------- final vj GEMM (fp16) ----------------
__global__ __launch_bounds__(128) void gemm_vj16(const __half* __restrict__ WctxT,
                                                 const float* __restrict__ bias,
                                                 const float* __restrict__ vf,
                                                 float* __restrict__ out) {
    extern __shared__ uint32_t sm16[];
    uint32_t* As = sm16;
    uint32_t* Bs = sm16 + NSTG * STG32;
    int bm = blockIdx.y * 128;
    int bn = blockIdx.x * 128;

    float acc[4][8][4];
#pragma unroll
    for (int a = 0; a < 4; a++)
#pragma unroll
        for (int b = 0; b < 8; b++)
#pragma unroll
            for (int c = 0; c < 4; c++) acc[a][b][c] = 0.f;

    run_ml16(g_ctx16, WctxT, bm, bn, 32, acc, As, Bs);

    int lane = threadIdx.x & 31;
    int warp = threadIdx.x >> 5;
    int wm = (warp & 1) * 64;
    int wn = (warp >> 1) * 64;
#pragma unroll
    for (int mt = 0; mt < 4; mt++)
#pragma unroll
        for (int half_ = 0; half_ < 2; half_++) {
            int r = bm + wm + mt * 16 + (lane >> 2) + half_ * 8;
            bool inv = (g_degS[r] + g_degO[r]) > 0;
            const float* vfr = vf + (size_t)r * DD;
            float* outr = out + (size_t)r * DD;
#pragma unroll
            for (int nt = 0; nt < 8; nt++) {
                int c = bn + wn + nt * 8 + (lane & 3) * 2;
                float2 v;
                v.x = vfr[c]     + acc[mt][nt][half_ * 2 + 0] + (inv ? bias[c] : 0.f);
                v.y = vfr[c + 1] + acc[mt][nt][half_ * 2 + 1] + (inv ? bias[c + 1] : 0.f);
                *(float2*)(outr + c) = v;
            }
        }
}

// ---------------- conversion kernels ----------------
__global__ void k_copyround(const float* __restrict__ src, float* __restrict__ raw) {
    int i = blockIdx.x * 256 + threadIdx.x;
    float4 v = ((const float4*)src)[i];
    ((float4*)raw)[i] = v;
    __half2 h0, h1;
    h0.x = __float2half_rn(v.x); h0.y = __float2half_rn(v.y);
    h1.x = __float2half_rn(v.z); h1.y = __float2half_rn(v.w);
    ((__half2*)g_R16)[2 * i] = h0;
    ((__half2*)g_R16)[2 * i + 1] = h1;
}
__global__ void k_roundh(const float* __restrict__ src, __half* __restrict__ dst, int n4) {
    int i = blockIdx.x * blockDim.x + threadIdx.x;
    if (i < n4) {
        float4 v = ((const float4*)src)[i];
        __half2 h0, h1;
        h0.x = __float2half_rn(v.x); h0.y = __float2half_rn(v.y);
        h1.x = __float2half_rn(v.z); h1.y = __float2half_rn(v.w);
        ((__half2*)dst)[2 * i] = h0;
        ((__half2*)dst)[2 * i + 1] = h1;
    }
}
struct TPair { const float* s; __half* d; };
struct TBatch { TPair p[5]; };
__global__ void k_troundh(TBatch tb) {
    __shared__ float t[32][33];
    TPair pr = tb.p[blockIdx.z];
    int x = blockIdx.x * 32 + threadIdx.x;
    int y0 = blockIdx.y * 32 + threadIdx.y;
#pragma unroll
    for (int j = 0; j < 4; j++)
        t[threadIdx.y + j * 8][threadIdx.x] = pr.s[(size_t)(y0 + j * 8) * DD + x];
    __syncthreads();
    int x2 = blockIdx.y * 32 + threadIdx.x;
    int y2 = blockIdx.x * 32 + threadIdx.y;
#pragma unroll
    for (int j = 0; j < 4; j++)
        pr.d[(size_t)(y2 + j * 8) * DD + x2] = __float2half_rn(t[threadIdx.x][threadIdx.y + j * 8]);
}

// ---------------- small kernels ----------------
__global__ void k_init() {
    int i = blockIdx.x * blockDim.x + threadIdx.x;
    if (i < EE) g_logits[i] = 0.f;
    if (i < NN) {
        g_sumS[i] = 0.f; g_sumO[i] = 0.f;
        g_maxS[i] = 0u; g_maxO[i] = 0u;
        g_degS[i] = 0; g_degO[i] = 0;
    }
}
__global__ void k_hist(const int* __restrict__ sbj, const int* __restrict__ obj) {
    int e = blockIdx.x * blockDim.x + threadIdx.x;
    if (e < EE) { atomicAdd(&g_degS[sbj[e]], 1); atomicAdd(&g_degO[obj[e]], 1); }
}
__global__ void k_scan() {
    __shared__ int wsumS[24], wsumO[24];
    int t = threadIdx.x;
    int lane = t & 31, warp = t >> 5;
    int dS = g_degS[t], dO = g_degO[t];
    int iS = dS, iO = dO;
#pragma unroll
    for (int off = 1; off < 32; off <<= 1) {
        int vS = __shfl_up_sync(0xFFFFFFFF, iS, off);
        int vO = __shfl_up_sync(0xFFFFFFFF, iO, off);
        if (lane >= off) { iS += vS; iO += vO; }
    }
    if (lane == 31) { wsumS[warp] = iS; wsumO[warp] = iO; }
    __syncthreads();
    if (warp == 0 && lane < 24) {
        int sS = wsumS[lane], sO = wsumO[lane];
#pragma unroll
        for (int off = 1; off < 32; off <<= 1) {
            int vS = __shfl_up_sync(0x00FFFFFF, sS, off);
            int vO = __shfl_up_sync(0x00FFFFFF, sO, off);
            if (lane >= off) { sS += vS; sO += vO; }
        }
        wsumS[lane] = sS; wsumO[lane] = sO;
    }
    __syncthreads();
    int offS = (warp > 0) ? wsumS[warp - 1] : 0;
    int offO = (warp > 0) ? wsumO[warp - 1] : 0;
    g_baseS[t] = offS + iS - dS;
    g_baseO[t] = offO + iO - dO;
    g_curO[t]  = offO + iO - dO;
}
__global__ void k_scatter(const int* __restrict__ obj) {
    int e = blockIdx.x * blockDim.x + threadIdx.x;
    if (e < EE) { int p = atomicAdd(&g_curO[obj[e]], 1); g_permO[p] = e; }
}
__global__ void k_vecs1p(const float* __restrict__ b_rel,
                         const float* __restrict__ Ws_r,
                         const float* __restrict__ Wo_r) {
    int j = blockIdx.x * 256 + threadIdx.x;
    int c = blockIdx.y;
    int i0 = c * 128;
    float s = 0.f, o = 0.f;
    for (int i = i0; i < i0 + 128; i++) {
        float br = b_rel[i];
        s += br * Ws_r[(size_t)i * DD + j];
        o += br * Wo_r[(size_t)i * DD + j];
    }
    g_csp[c * DD + j] = s;
    g_cop[c * DD + j] = o;
}
__global__ void k_vecs1r(const float* __restrict__ b_sbj, const float* __restrict__ b_obj) {
    int j = blockIdx.x * 256 + threadIdx.x;
    float s = b_sbj[j], o = b_obj[j];
#pragma unroll
    for (int c = 0; c < 8; c++) {
        s += g_csp[c * DD + j];
        o += g_cop[c * DD + j];
    }
    g_cs[j] = s;
    g_co[j] = o;
}
__global__ void k_c3() {
    int j = blockIdx.x * 8 + (threadIdx.x >> 5);
    int lane = threadIdx.x & 31;
    if (j >= DD) return;
    float a = 0.f;
    for (int i = lane; i < DD; i += 32)
        a += g_cs[i] * __half2float(g_Ho16[(size_t)j * DD + i])
           + g_co[i] * __half2float(g_Hs16[(size_t)j * DD + i]);
#pragma unroll
    for (int off = 16; off > 0; off >>= 1) a += __shfl_xor_sync(0xFFFFFFFF, a, off);
    if (lane == 0) g_c3[j] = a;
}
__global__ void k_scal() {
    int n = blockIdx.x * 8 + (threadIdx.x >> 5);
    int lane = threadIdx.x & 31;
    if (n >= NN) return;
    const __half* Ts = g_T16 + 0 * NN * DD + (size_t)n * DD;
    const __half* Us = g_T16 + 1 * NN * DD + (size_t)n * DD;
    const __half* To = g_T16 + 2 * NN * DD + (size_t)n * DD;
    const __half* Uo = g_T16 + 3 * NN * DD + (size_t)n * DD;
    float t1 = 0.f, t2 = 0.f, t3 = 0.f;
    for (int c = lane; c < DD; c += 32) {
        float cs = g_cs[c], co = g_co[c];
        t1 += (__half2float(Ts[c]) + cs) * (__half2float(Uo[c]) + co);
        t2 += (__half2float(Us[c]) + cs) * (__half2float(To[c]) + co);
        t3 += cs * co;
    }
#pragma unroll
    for (int off = 16; off > 0; off >>= 1) {
        t1 += __shfl_xor_sync(0xFFFFFFFF, t1, off);
        t2 += __shfl_xor_sync(0xFFFFFFFF, t2, off);
        t3 += __shfl_xor_sync(0xFFFFFFFF, t3, off);
    }
    if (lane == 0) { g_d1[n] = t1; g_d2[n] = t2 - t3; }
}
__global__ void k_max(const int* __restrict__ sbj, const int* __restrict__ obj) {
    int e = blockIdx.x * blockDim.x + threadIdx.x;
    if (e < EE) {
        unsigned k = fkey(g_logits[e]);
        atomicMax(&g_maxS[sbj[e]], k);
        atomicMax(&g_maxO[obj[e]], k);
    }
}
__global__ void k_exp(const int* __restrict__ sbj, const int* __restrict__ obj) {
    int e = blockIdx.x * blockDim.x + threadIdx.x;
    if (e < EE) {
        float l = g_logits[e];
        float es = expf(l - funkey(g_maxS[sbj[e]]));
        float eo = expf(l - funkey(g_maxO[obj[e]]));
        g_wS[e] = es; g_wO[e] = eo;
        atomicAdd(&g_sumS[sbj[e]], es);
        atomicAdd(&g_sumO[obj[e]], eo);
    }
}
// merged ctx: per node, S-aggregation then O-aggregation, write fp16 only
__global__ void k_ctx(const int* __restrict__ sbj, const int* __restrict__ obj,
                      const float* __restrict__ vf) {
    int n = blockIdx.x, t = threadIdx.x;
    const float4* vf4 = (const float4*)vf;
    float4 res = make_float4(0.f, 0.f, 0.f, 0.f);
    int cntS = g_degS[n];
    if (cntS > 0) {
        int beg = g_baseS[n];
        float inv = 1.f / g_sumS[n];
        float4 acc = make_float4(0.f, 0.f, 0.f, 0.f);
        for (int i = 0; i < cntS; i++) {
            int e = beg + i;
            float w = g_wS[e];
            float4 v = vf4[(size_t)obj[e] * 256 + t];
            acc.x += w * v.x; acc.y += w * v.y; acc.z += w * v.z; acc.w += w * v.w;
        }
        res.x = acc.x * inv; res.y = acc.y * inv; res.z = acc.z * inv; res.w = acc.w * inv;
    }
    int cntO = g_degO[n];
    if (cntO > 0) {
        int beg = g_baseO[n];
        float inv = 1.f / g_sumO[n];
        float4 acc = make_float4(0.f, 0.f, 0.f, 0.f);
        for (int i = 0; i < cntO; i++) {
            int e = g_permO[beg + i];
            float w = g_wO[e];
            float4 v = vf4[(size_t)sbj[e] * 256 + t];
            acc.x += w * v.x; acc.y += w * v.y; acc.z += w * v.z; acc.w += w * v.w;
        }
        res.x += acc.x * inv; res.y += acc.y * inv; res.z += acc.z * inv; res.w += acc.w * inv;
    }
    __half2 h0, h1;
    h0.x = __float2half_rn(res.x); h0.y = __float2half_rn(res.y);
    h1.x = __float2half_rn(res.z); h1.y = __float2half_rn(res.w);
    ((__half2*)g_ctx16)[(size_t)n * 512 + 2 * t]     = h0;
    ((__half2*)g_ctx16)[(size_t)n * 512 + 2 * t + 1] = h1;
}

// ---------------- launch ----------------
extern "C" void kernel_launch(void* const* d_in, const int* in_sizes, int n_in,
                              void* d_out, int out_size) {
    const float* vf    = (const float*)d_in[0];
    const float* R     = (const float*)d_in[1];
    const float* W_rel = (const float*)d_in[2];
    const float* b_rel = (const float*)d_in[3];
    const float* W_sbj = (const float*)d_in[4];
    const float* b_sbj = (const float*)d_in[5];
    const float* W_obj = (const float*)d_in[6];
    const float* b_obj = (const float*)d_in[7];
    const float* W_ctx = (const float*)d_in[8];
    const float* b_ctx = (const float*)d_in[9];
    const int* sbj     = (const int*)d_in[10];
    const int* obj     = (const int*)d_in[11];
    float* out = (float*)d_out;

    cudaFuncSetAttribute(gemm_multi,   cudaFuncAttributeMaxDynamicSharedMemorySize, SMEM16_BYTES);
    cudaFuncSetAttribute(gemm_logit16, cudaFuncAttributeMaxDynamicSharedMemorySize, SMEM16_BYTES);
    cudaFuncSetAttribute(gemm_vj16,    cudaFuncAttributeMaxDynamicSharedMemorySize, SMEM16_BYTES);

    __half *pHs, *pHo, *pKt, *pMT, *pT, *pWr, *pWT, *pVf;
    cudaGetSymbolAddress((void**)&pHs, g_Hs16);
    cudaGetSymbolAddress((void**)&pHo, g_Ho16);
    cudaGetSymbolAddress((void**)&pKt, g_Kt16);
    cudaGetSymbolAddress((void**)&pMT, g_MT16);
    cudaGetSymbolAddress((void**)&pT,  g_T16);
    cudaGetSymbolAddress((void**)&pWr, g_Wr16);
    cudaGetSymbolAddress((void**)&pWT, g_WT16);
    cudaGetSymbolAddress((void**)&pVf, g_vf16);
    float *pS1, *pS2, *pG, *pC3;
    cudaGetSymbolAddress((void**)&pS1, g_S1);
    cudaGetSymbolAddress((void**)&pS2, g_S2);
    cudaGetSymbolAddress((void**)&pG,  g_G);
    cudaGetSymbolAddress((void**)&pC3, g_c3);

    const __half* hWr_s = pWr + 0 * (size_t)DD * DD;
    const __half* hWr_o = pWr + 1 * (size_t)DD * DD;
    const __half* hWr_r = pWr + 2 * (size_t)DD * DD;
    __half* hWs_rT = pWT + 0 * (size_t)DD * DD;
    __half* hWo_rT = pWT + 1 * (size_t)DD * DD;
    __half* hWctxT = pWT + 2 * (size_t)DD * DD;
    __half* hWs_vT = pWT + 3 * (size_t)DD * DD;
    __half* hWo_vT = pWT + 4 * (size_t)DD * DD;

    const float* Ws_v = W_sbj;
    const float* Ws_r = W_sbj + (size_t)DD * DD;
    const float* Wo_v = W_obj;
    const float* Wo_r = W_obj + (size_t)DD * DD;

    k_copyround<<<EE * DD / 4 / 256, 256>>>(R, out);

    k_init<<<(EE + 255) / 256, 256>>>();
    k_hist<<<(EE + 255) / 256, 256>>>(sbj, obj);
    k_scan<<<1, 768>>>();
    k_scatter<<<(EE + 255) / 256, 256>>>(obj);
    k_vecs1p<<<dim3(4, 8), 256>>>(b_rel, Ws_r, Wo_r);
    k_vecs1r<<<4, 256>>>(b_sbj, b_obj);

    k_roundh<<<(3 * DD * DD / 4 + 255) / 256, 256>>>(W_rel, pWr, 3 * DD * DD / 4);
    k_roundh<<<(NN * DD / 4 + 255) / 256, 256>>>(vf, pVf, NN * DD / 4);
    {
        TBatch tb{};
        tb.p[0] = {Ws_r,  hWs_rT};
        tb.p[1] = {Wo_r,  hWo_rT};
        tb.p[2] = {W_ctx, hWctxT};
        tb.p[3] = {Ws_v,  hWs_vT};
        tb.p[4] = {Wo_v,  hWo_vT};
        k_troundh<<<dim3(32, 32, 5), dim3(32, 8)>>>(tb);
    }

    // L1: Hs, Ho, M1T..M4T
    {
        Batch b{};
        b.d[0] = {hWr_r,  hWs_rT, nullptr, nullptr, nullptr, nullptr, nullptr, pHs,                        DD, DD, DD, 0};
        b.d[1] = {hWr_r,  hWo_rT, nullptr, nullptr, nullptr, nullptr, nullptr, pHo,                        DD, DD, DD, 0};
        b.d[2] = {hWs_rT, hWr_s,  nullptr, nullptr, hWs_vT,  nullptr, nullptr, pMT + 0 * (size_t)DD * DD,  DD, DD, DD, 0};
        b.d[3] = {hWs_rT, hWr_o,  nullptr, nullptr, nullptr, nullptr, nullptr, pMT + 1 * (size_t)DD * DD,  DD, DD, DD, 0};
        b.d[4] = {hWo_rT, hWr_o,  nullptr, nullptr, hWo_vT,  nullptr, nullptr, pMT + 2 * (size_t)DD * DD,  DD, DD, DD, 0};
        b.d[5] = {hWo_rT, hWr_s,  nullptr, nullptr, nullptr, nullptr, nullptr, pMT + 3 * (size_t)DD * DD,  DD, DD, DD, 0};
        gemm_multi<<<dim3(8, 8, 6), 128, SMEM16_BYTES>>>(b);
    }
    // c3 from Hs/Ho (before L3 consumes it)
    k_c3<<<128, 256>>>();
    // L2: T_z (M=768) + Kt
    {
        Batch b{};
        for (int z = 0; z < 4; z++)
            b.d[z] = {pVf, pMT + (size_t)z * DD * DD, nullptr, nullptr, nullptr, nullptr, nullptr,
                      pT + (size_t)z * NN * DD, NN, DD, DD, 0};
        b.d[4] = {pHo, pHs, nullptr, nullptr, nullptr, nullptr, nullptr, pKt, DD, DD, DD, 0};
        gemm_multi<<<dim3(8, 8, 5), 128, SMEM16_BYTES>>>(b);
    }
    // L3: S1 (+c3 row), S2, G
    {
        Batch b{};
        b.d[0] = {pT + 0 * (size_t)NN * DD, pHo, pT + 3 * (size_t)NN * DD, pHs, nullptr, pC3, pS1, nullptr,
                  NN, DD, DD, 1};
        b.d[1] = {pT + 1 * (size_t)NN * DD, pHo, pT + 2 * (size_t)NN * DD, pHs, nullptr, nullptr, pS2, nullptr,
                  NN, DD, DD, 1};
        b.d[2] = {pT + 0 * (size_t)NN * DD, pT + 2 * (size_t)NN * DD,
                  pT + 3 * (size_t)NN * DD, pT + 1 * (size_t)NN * DD, nullptr, nullptr, pG, nullptr,
                  NN, NN, NN, 1};
        gemm_multi<<<dim3(8, 6, 3), 128, SMEM16_BYTES>>>(b);
    }
    k_scal<<<96, 256>>>();

    gemm_logit16<<<dim3(8, 192, 2), 128, SMEM16_BYTES>>>(sbj, obj);

    k_max<<<(EE + 255) / 256, 256>>>(sbj, obj);
    k_exp<<<(EE + 255) / 256, 256>>>(sbj, obj);
    k_ctx<<<NN, 256>>>(sbj, obj, vf);

    gemm_vj16<<<dim3(8, 6), 128, SMEM16_BYTES>>>(hWctxT, b_ctx, vf, out + (size_t)EE * DD);

    (void)in_sizes; (void)n_in; (void)out_size;
}

// round 16
// speedup vs baseline: 1.0032x; 1.0032x over previous
#include <cuda_runtime.h>
#include <cuda_fp16.h>
#include <math.h>
#include <cstdint>

#define NN 768
#define EE 24576
#define DD 1024

// ---------------- fp16 GEMM operand scratch (all [x][1024] K-major) ----------------
__device__ __align__(128) __half g_Hs16[DD * DD];
__device__ __align__(128) __half g_Ho16[DD * DD];
__device__ __align__(128) __half g_Kt16[DD * DD];
__device__ __align__(128) __half g_MT16[4 * DD * DD];
__device__ __align__(128) __half g_T16 [4 * NN * DD];
__device__ __align__(128) __half g_Wr16[3 * DD * DD];
__device__ __align__(128) __half g_WT16[5 * DD * DD];
__device__ __align__(128) __half g_vf16[NN * DD];
__device__ __align__(128) __half g_R16 [(size_t)EE * DD];
__device__ __align__(128) __half g_ctx16[NN * DD];
// ---------------- fp32 scratch ----------------
__device__ __align__(128) float g_S1[NN * DD];
__device__ __align__(128) float g_S2[NN * DD];
__device__ __align__(128) float g_G [NN * NN];
__device__ float g_cs[DD], g_co[DD], g_c3[DD];
__device__ float g_csp[8 * DD], g_cop[8 * DD];
__device__ float g_d1[NN], g_d2[NN];
__device__ __align__(128) float g_logits[EE];
__device__ __align__(128) float g_wS[EE];
__device__ __align__(128) float g_wO[EE];
__device__ unsigned g_maxS[NN], g_maxO[NN];
__device__ float g_sumS[NN], g_sumO[NN];
__device__ int g_degS[NN], g_degO[NN], g_baseS[NN], g_baseO[NN], g_curO[NN];
__device__ int g_permO[EE];

#define STR32 20
#define STG32 (128 * STR32)
#define NSTG 4
#define SMEM16_BYTES (NSTG * 2 * STG32 * 4)  // 81920 B

// ---------------- helpers ----------------
__device__ __forceinline__ void mma16(float c[4], unsigned a0, unsigned a1, unsigned a2, unsigned a3,
                                      unsigned b0, unsigned b1) {
    asm volatile(
        "mma.sync.aligned.m16n8k16.row.col.f32.f16.f16.f32 "
        "{%0,%1,%2,%3},{%4,%5,%6,%7},{%8,%9},{%0,%1,%2,%3};"
        : "+f"(c[0]), "+f"(c[1]), "+f"(c[2]), "+f"(c[3])
        : "r"(a0), "r"(a1), "r"(a2), "r"(a3), "r"(b0), "r"(b1));
}
__device__ __forceinline__ void ldsm4(unsigned& r0, unsigned& r1, unsigned& r2, unsigned& r3, uint32_t addr) {
    asm volatile("ldmatrix.sync.aligned.m8n8.x4.shared.b16 {%0,%1,%2,%3}, [%4];"
        : "=r"(r0), "=r"(r1), "=r"(r2), "=r"(r3) : "r"(addr));
}
__device__ __forceinline__ void cpa16p(void* s, const void* g) {
    unsigned sa = (unsigned)__cvta_generic_to_shared(s);
    asm volatile("cp.async.cg.shared.global [%0], [%1], 16;" :: "r"(sa), "l"(g));
}
__device__ __forceinline__ void cpa_commit() { asm volatile("cp.async.commit_group;"); }
template<int N> __device__ __forceinline__ void cpa_wait() { asm volatile("cp.async.wait_group %0;" :: "n"(N)); }

__device__ __forceinline__ unsigned fkey(float f) {
    unsigned u = __float_as_uint(f);
    return (u & 0x80000000u) ? ~u : (u | 0x80000000u);
}
__device__ __forceinline__ float funkey(unsigned k) {
    return (k & 0x80000000u) ? __uint_as_float(k ^ 0x80000000u) : __uint_as_float(~k);
}

// ---------------- fp16 NT mainloop (ldmatrix, 4-stage, nk slabs) ----------------
__device__ __forceinline__ void run_ml16(const __half* __restrict__ A,
                                         const __half* __restrict__ B,
                                         int bm, int bn, int nk,
                                         float (&acc)[4][8][4],
                                         uint32_t* __restrict__ As,
                                         uint32_t* __restrict__ Bs) {
    int tid = threadIdx.x;
    int lane = tid & 31;
    int warp = tid >> 5;
    int wm = (warp & 1) * 64;
    int wn = (warp >> 1) * 64;

    uint32_t baseA = (uint32_t)__cvta_generic_to_shared(As);
    uint32_t baseB = (uint32_t)__cvta_generic_to_shared(Bs);

    uint32_t offA[4], offB[4];
#pragma unroll
    for (int mt = 0; mt < 4; mt++)
        offA[mt] = (uint32_t)((wm + mt * 16 + (lane & 7) + ((lane >> 3) & 1) * 8) * 80 + (lane >> 4) * 16);
#pragma unroll
    for (int p = 0; p < 4; p++)
        offB[p] = (uint32_t)((wn + p * 16 + (lane & 7) + ((lane >> 4) & 1) * 8) * 80 + ((lane >> 3) & 1) * 16);

    auto issue = [&](int s) {
        int stg = s % NSTG;
        uint32_t* as = As + stg * STG32;
        uint32_t* bs = Bs + stg * STG32;
#pragma unroll
        for (int p = 0; p < 4; p++) {
            int idx = p * 128 + tid;
            int row = idx >> 2;
            int c4 = idx & 3;
            cpa16p(as + row * STR32 + c4 * 4, A + (size_t)(bm + row) * DD + s * 32 + c4 * 8);
        }
#pragma unroll
        for (int p = 0; p < 4; p++) {
            int idx = p * 128 + tid;
            int row = idx >> 2;
            int c4 = idx & 3;
            cpa16p(bs + row * STR32 + c4 * 4, B + (size_t)(bn + row) * DD + s * 32 + c4 * 8);
        }
        cpa_commit();
    };

    issue(0);
    issue(1);
    issue(2);
    for (int kt = 0; kt < nk; kt++) {
        cpa_wait<2>();
        __syncthreads();
        uint32_t ta = baseA + (uint32_t)((kt % NSTG) * STG32 * 4);
        uint32_t tb = baseB + (uint32_t)((kt % NSTG) * STG32 * 4);
#pragma unroll
        for (int kk = 0; kk < 2; kk++) {
            unsigned af[4][4], bf[8][2];
#pragma unroll
            for (int mt = 0; mt < 4; mt++)
                ldsm4(af[mt][0], af[mt][1], af[mt][2], af[mt][3], ta + offA[mt] + kk * 32);
#pragma unroll
            for (int p = 0; p < 4; p++)
                ldsm4(bf[2 * p][0], bf[2 * p][1], bf[2 * p + 1][0], bf[2 * p + 1][1],
                      tb + offB[p] + kk * 32);
#pragma unroll
            for (int mt = 0; mt < 4; mt++)
#pragma unroll
                for (int nt = 0; nt < 8; nt++)
                    mma16(acc[mt][nt], af[mt][0], af[mt][1], af[mt][2], af[mt][3],
                          bf[nt][0], bf[nt][1]);
        }
        if (kt + 3 < nk) issue(kt + 3);
    }
}

// ---------------- generalized batched NT GEMM ----------------
struct Desc {
    const __half* A; const __half* B; const __half* A2; const __half* B2;
    const __half* CaddH;          // optional half addend [m][n]
    const float* CaddRow;         // optional broadcast row addend [n]
    float* C32; __half* C16;      // exactly one non-null
    int M; int N; int ldc; int dual;
};
struct Batch { Desc d[6]; };

__global__ __launch_bounds__(128) void gemm_multi(Batch p) {
    Desc d = p.d[blockIdx.z];
    int bm = blockIdx.y * 128;
    int bn = blockIdx.x * 128;
    if (bm >= d.M || bn >= d.N) return;

    extern __shared__ uint32_t sm16[];
    uint32_t* As = sm16;
    uint32_t* Bs = sm16 + NSTG * STG32;

    float acc[4][8][4];
#pragma unroll
    for (int a = 0; a < 4; a++)
#pragma unroll
        for (int b = 0; b < 8; b++)
#pragma unroll
            for (int c = 0; c < 4; c++) acc[a][b][c] = 0.f;

    run_ml16(d.A, d.B, bm, bn, 32, acc, As, Bs);
    if (d.dual) { __syncthreads(); run_ml16(d.A2, d.B2, bm, bn, 32, acc, As, Bs); }

    int lane = threadIdx.x & 31;
    int warp = threadIdx.x >> 5;
    int wm = (warp & 1) * 64;
    int wn = (warp >> 1) * 64;
#pragma unroll
    for (int mt = 0; mt < 4; mt++)
#pragma unroll
        for (int half_ = 0; half_ < 2; half_++) {
            int r = bm + wm + mt * 16 + (lane >> 2) + half_ * 8;
#pragma unroll
            for (int nt = 0; nt < 8; nt++) {
                int c = bn + wn + nt * 8 + (lane & 3) * 2;
                float vx = acc[mt][nt][half_ * 2 + 0];
                float vy = acc[mt][nt][half_ * 2 + 1];
                if (d.CaddH) {
                    vx += __half2float(d.CaddH[(size_t)r * d.ldc + c]);
                    vy += __half2float(d.CaddH[(size_t)r * d.ldc + c + 1]);
                }
                if (d.CaddRow) {
                    vx += d.CaddRow[c];
                    vy += d.CaddRow[c + 1];
                }
                if (d.C16) {
                    __half2 h;
                    h.x = __float2half_rn(vx);
                    h.y = __float2half_rn(vy);
                    *(__half2*)(d.C16 + (size_t)r * d.ldc + c) = h;
                } else {
                    float2 v; v.x = vx; v.y = vy;
                    *(float2*)(d.C32 + (size_t)r * d.ldc + c) = v;
                }
            }
        }
}

// ---------------- E-GEMM (fp16) with fused logit epilogue, split-K2 ----------------
__global__ __launch_bounds__(128) void gemm_logit16(const int* __restrict__ sbj,
                                                    const int* __restrict__ obj) {
    extern __shared__ uint32_t sm16[];
    uint32_t* As = sm16;
    uint32_t* Bs = sm16 + NSTG * STG32;
    int bm = blockIdx.y * 128;
    int bn = blockIdx.x * 128;
    int kz = blockIdx.z;           // 0 or 1, K halves

    float acc[4][8][4];
#pragma unroll
    for (int a = 0; a < 4; a++)
#pragma unroll
        for (int b = 0; b < 8; b++)
#pragma unroll
            for (int c = 0; c < 4; c++) acc[a][b][c] = 0.f;

    run_ml16(g_R16 + kz * 512, g_Kt16 + kz * 512, bm, bn, 16, acc, As, Bs);

    int lane = threadIdx.x & 31;
    int warp = threadIdx.x >> 5;
    int wm = (warp & 1) * 64;
    int wn = (warp >> 1) * 64;
    const float scale = 0.03125f;

#pragma unroll
    for (int mt = 0; mt < 4; mt++) {
#pragma unroll
        for (int half_ = 0; half_ < 2; half_++) {
            int r = bm + wm + mt * 16 + (lane >> 2) + half_ * 8;
            int s = sbj[r], o = obj[r];
            const __half2* Rr = (const __half2*)(g_R16 + (size_t)r * DD);
            const float* S1r = g_S1 + (size_t)s * DD;
            const float* S2r = g_S2 + (size_t)o * DD;
            float part = 0.f;
#pragma unroll
            for (int nt = 0; nt < 8; nt++) {
                int c = bn + wn + nt * 8 + (lane & 3) * 2;
                float2 Rv = __half22float2(Rr[c >> 1]);
                float sx = 0.f, sy = 0.f;
                if (kz == 1) {
                    float2 s1v = *(const float2*)(S1r + c);
                    float2 s2v = *(const float2*)(S2r + c);
                    sx = s1v.x + s2v.x;
                    sy = s1v.y + s2v.y;
                }
                part += (acc[mt][nt][half_ * 2 + 0] + sx) * Rv.x;
                part += (acc[mt][nt][half_ * 2 + 1] + sy) * Rv.y;
            }
            part += __shfl_xor_sync(0xFFFFFFFF, part, 1);
            part += __shfl_xor_sync(0xFFFFFFFF, part, 2);
            if ((lane & 3) == 0) {
                if (kz == 1 && bn == 0 && wn == 0)
                    part += g_G[(size_t)s * NN + o] + g_d1[s] + g_d2[o];
                atomicAdd(&g_logits[r], part * scale);
            }
        }
    }
}

// ---------------- final vj GEMM (fp16) ----------------
__global__ __launch_bounds__(128) void gemm_vj16(const __half* __restrict__ WctxT,
                                                 const float* __restrict__ bias,
                                                 const float* __restrict__ vf,
                                                 float* __restrict__ out) {
    extern __shared__ uint32_t sm16[];
    uint32_t* As = sm16;
    uint32_t* Bs = sm16 + NSTG * STG32;
    int bm = blockIdx.y * 128;
    int bn = blockIdx.x * 128;

    float acc[4][8][4];
#pragma unroll
    for (int a = 0; a < 4; a++)
#pragma unroll
        for (int b = 0; b < 8; b++)
#pragma unroll
            for (int c = 0; c < 4; c++) acc[a][b][c] = 0.f;

    run_ml16(g_ctx16, WctxT, bm, bn, 32, acc, As, Bs);

    int lane = threadIdx.x & 31;
    int warp = threadIdx.x >> 5;
    int wm = (warp & 1) * 64;
    int wn = (warp >> 1) * 64;
#pragma unroll
    for (int mt = 0; mt < 4; mt++)
#pragma unroll
        for (int half_ = 0; half_ < 2; half_++) {
            int r = bm + wm + mt * 16 + (lane >> 2) + half_ * 8;
            bool inv = (g_degS[r] + g_degO[r]) > 0;
            const float* vfr = vf + (size_t)r * DD;
            float* outr = out + (size_t)r * DD;
#pragma unroll
            for (int nt = 0; nt < 8; nt++) {
                int c = bn + wn + nt * 8 + (lane & 3) * 2;
                float2 v;
                v.x = vfr[c]     + acc[mt][nt][half_ * 2 + 0] + (inv ? bias[c] : 0.f);
                v.y = vfr[c + 1] + acc[mt][nt][half_ * 2 + 1] + (inv ? bias[c + 1] : 0.f);
                *(float2*)(outr + c) = v;
            }
        }
}

// ---------------- conversion kernels ----------------
__global__ void k_copyround(const float* __restrict__ src, float* __restrict__ raw) {
    int i = blockIdx.x * 256 + threadIdx.x;
    float4 v = ((const float4*)src)[i];
    ((float4*)raw)[i] = v;
    __half2 h0, h1;
    h0.x = __float2half_rn(v.x); h0.y = __float2half_rn(v.y);
    h1.x = __float2half_rn(v.z); h1.y = __float2half_rn(v.w);
    ((__half2*)g_R16)[2 * i] = h0;
    ((__half2*)g_R16)[2 * i + 1] = h1;
}
__global__ void k_roundh(const float* __restrict__ src, __half* __restrict__ dst, int n4) {
    int i = blockIdx.x * blockDim.x + threadIdx.x;
    if (i < n4) {
        float4 v = ((const float4*)src)[i];
        __half2 h0, h1;
        h0.x = __float2half_rn(v.x); h0.y = __float2half_rn(v.y);
        h1.x = __float2half_rn(v.z); h1.y = __float2half_rn(v.w);
        ((__half2*)dst)[2 * i] = h0;
        ((__half2*)dst)[2 * i + 1] = h1;
    }
}
struct TPair { const float* s; __half* d; };
struct TBatch { TPair p[5]; };
__global__ void k_troundh(TBatch tb) {
    __shared__ float t[32][33];
    TPair pr = tb.p[blockIdx.z];
    int x = blockIdx.x * 32 + threadIdx.x;
    int y0 = blockIdx.y * 32 + threadIdx.y;
#pragma unroll
    for (int j = 0; j < 4; j++)
        t[threadIdx.y + j * 8][threadIdx.x] = pr.s[(size_t)(y0 + j * 8) * DD + x];
    __syncthreads();
    int x2 = blockIdx.y * 32 + threadIdx.x;
    int y2 = blockIdx.x * 32 + threadIdx.y;
#pragma unroll
    for (int j = 0; j < 4; j++)
        pr.d[(size_t)(y2 + j * 8) * DD + x2] = __float2half_rn(t[threadIdx.x][threadIdx.y + j * 8]);
}

// ---------------- small kernels ----------------
__global__ void k_init() {
    int i = blockIdx.x * blockDim.x + threadIdx.x;
    if (i < EE) g_logits[i] = 0.f;
    if (i < NN) {
        g_sumS[i] = 0.f; g_sumO[i] = 0.f;
        g_maxS[i] = 0u; g_maxO[i] = 0u;
        g_degS[i] = 0; g_degO[i] = 0;
    }
}
__global__ void k_hist(const int* __restrict__ sbj, const int* __restrict__ obj) {
    int e = blockIdx.x * blockDim.x + threadIdx.x;
    if (e < EE) { atomicAdd(&g_degS[sbj[e]], 1); atomicAdd(&g_degO[obj[e]], 1); }
}
__global__ void k_scan() {
    __shared__ int wsumS[24], wsumO[24];
    int t = threadIdx.x;
    int lane = t & 31, warp = t >> 5;
    int dS = g_degS[t], dO = g_degO[t];
    int iS = dS, iO = dO;
#pragma unroll
    for (int off = 1; off < 32; off <<= 1) {
        int vS = __shfl_up_sync(0xFFFFFFFF, iS, off);
        int vO = __shfl_up_sync(0xFFFFFFFF, iO, off);
        if (lane >= off) { iS += vS; iO += vO; }
    }
    if (lane == 31) { wsumS[warp] = iS; wsumO[warp] = iO; }
    __syncthreads();
    if (warp == 0 && lane < 24) {
        int sS = wsumS[lane], sO = wsumO[lane];
#pragma unroll
        for (int off = 1; off < 32; off <<= 1) {
            int vS = __shfl_up_sync(0x00FFFFFF, sS, off);
            int vO = __shfl_up_sync(0x00FFFFFF, sO, off);
            if (lane >= off) { sS += vS; sO += vO; }
        }
        wsumS[lane] = sS; wsumO[lane] = sO;
    }
    __syncthreads();
    int offS = (warp > 0) ? wsumS[warp - 1] : 0;
    int offO = (warp > 0) ? wsumO[warp - 1] : 0;
    g_baseS[t] = offS + iS - dS;
    g_baseO[t] = offO + iO - dO;
    g_curO[t]  = offO + iO - dO;
}
__global__ void k_scatter(const int* __restrict__ obj) {
    int e = blockIdx.x * blockDim.x + threadIdx.x;
    if (e < EE) { int p = atomicAdd(&g_curO[obj[e]], 1); g_permO[p] = e; }
}
__global__ void k_vecs1p(const float* __restrict__ b_rel,
                         const float* __restrict__ Ws_r,
                         const float* __restrict__ Wo_r) {
    int j = blockIdx.x * 256 + threadIdx.x;
    int c = blockIdx.y;
    int i0 = c * 128;
    float s = 0.f, o = 0.f;
    for (int i = i0; i < i0 + 128; i++) {
        float br = b_rel[i];
        s += br * Ws_r[(size_t)i * DD + j];
        o += br * Wo_r[(size_t)i * DD + j];
    }
    g_csp[c * DD + j] = s;
    g_cop[c * DD + j] = o;
}
__global__ void k_vecs1r(const float* __restrict__ b_sbj, const float* __restrict__ b_obj) {
    int j = blockIdx.x * 256 + threadIdx.x;
    float s = b_sbj[j], o = b_obj[j];
#pragma unroll
    for (int c = 0; c < 8; c++) {
        s += g_csp[c * DD + j];
        o += g_cop[c * DD + j];
    }
    g_cs[j] = s;
    g_co[j] = o;
}
__global__ void k_c3() {
    int j = blockIdx.x * 8 + (threadIdx.x >> 5);
    int lane = threadIdx.x & 31;
    if (j >= DD) return;
    float a = 0.f;
    for (int i = lane; i < DD; i += 32)
        a += g_cs[i] * __half2float(g_Ho16[(size_t)j * DD + i])
           + g_co[i] * __half2float(g_Hs16[(size_t)j * DD + i]);
#pragma unroll
    for (int off = 16; off > 0; off >>= 1) a += __shfl_xor_sync(0xFFFFFFFF, a, off);
    if (lane == 0) g_c3[j] = a;
}
__global__ void k_scal() {
    int n = blockIdx.x * 8 + (threadIdx.x >> 5);
    int lane = threadIdx.x & 31;
    if (n >= NN) return;
    const __half* Ts = g_T16 + 0 * NN * DD + (size_t)n * DD;
    const __half* Us = g_T16 + 1 * NN * DD + (size_t)n * DD;
    const __half* To = g_T16 + 2 * NN * DD + (size_t)n * DD;
    const __half* Uo = g_T16 + 3 * NN * DD + (size_t)n * DD;
    float t1 = 0.f, t2 = 0.f, t3 = 0.f;
    for (int c = lane; c < DD; c += 32) {
        float cs = g_cs[c], co = g_co[c];
        t1 += (__half2float(Ts[c]) + cs) * (__half2float(Uo[c]) + co);
        t2 += (__half2float(Us[c]) + cs) * (__half2float(To[c]) + co);
        t3 += cs * co;
    }
#pragma unroll
    for (int off = 16; off > 0; off >>= 1) {
        t1 += __shfl_xor_sync(0xFFFFFFFF, t1, off);
        t2 += __shfl_xor_sync(0xFFFFFFFF, t2, off);
        t3 += __shfl_xor_sync(0xFFFFFFFF, t3, off);
    }
    if (lane == 0) { g_d1[n] = t1; g_d2[n] = t2 - t3; }
}
__global__ void k_max(const int* __restrict__ sbj, const int* __restrict__ obj) {
    int e = blockIdx.x * blockDim.x + threadIdx.x;
    if (e < EE) {
        unsigned k = fkey(g_logits[e]);
        atomicMax(&g_maxS[sbj[e]], k);
        atomicMax(&g_maxO[obj[e]], k);
    }
}
__global__ void k_exp(const int* __restrict__ sbj, const int* __restrict__ obj) {
    int e = blockIdx.x * blockDim.x + threadIdx.x;
    if (e < EE) {
        float l = g_logits[e];
        float es = expf(l - funkey(g_maxS[sbj[e]]));
        float eo = expf(l - funkey(g_maxO[obj[e]]));
        g_wS[e] = es; g_wO[e] = eo;
        atomicAdd(&g_sumS[sbj[e]], es);
        atomicAdd(&g_sumO[obj[e]], eo);
    }
}
// merged ctx: per node, S-aggregation then O-aggregation, write fp16 only
__global__ void k_ctx(const int* __restrict__ sbj, const int* __restrict__ obj,
                      const float* __restrict__ vf) {
    int n = blockIdx.x, t = threadIdx.x;
    const float4* vf4 = (const float4*)vf;
    float4 res = make_float4(0.f, 0.f, 0.f, 0.f);
    int cntS = g_degS[n];
    if (cntS > 0) {
        int beg = g_baseS[n];
        float inv = 1.f / g_sumS[n];
        float4 acc = make_float4(0.f, 0.f, 0.f, 0.f);
        for (int i = 0; i < cntS; i++) {
            int e = beg + i;
            float w = g_wS[e];
            float4 v = vf4[(size_t)obj[e] * 256 + t];
            acc.x += w * v.x; acc.y += w * v.y; acc.z += w * v.z; acc.w += w * v.w;
        }
        res.x = acc.x * inv; res.y = acc.y * inv; res.z = acc.z * inv; res.w = acc.w * inv;
    }
    int cntO = g_degO[n];
    if (cntO > 0) {
        int beg = g_baseO[n];
        float inv = 1.f / g_sumO[n];
        float4 acc = make_float4(0.f, 0.f, 0.f, 0.f);
        for (int i = 0; i < cntO; i++) {
            int e = g_permO[beg + i];
            float w = g_wO[e];
            float4 v = vf4[(size_t)sbj[e] * 256 + t];
            acc.x += w * v.x; acc.y += w * v.y; acc.z += w * v.z; acc.w += w * v.w;
        }
        res.x += acc.x * inv; res.y += acc.y * inv; res.z += acc.z * inv; res.w += acc.w * inv;
    }
    __half2 h0, h1;
    h0.x = __float2half_rn(res.x); h0.y = __float2half_rn(res.y);
    h1.x = __float2half_rn(res.z); h1.y = __float2half_rn(res.w);
    ((__half2*)g_ctx16)[(size_t)n * 512 + 2 * t]     = h0;
    ((__half2*)g_ctx16)[(size_t)n * 512 + 2 * t + 1] = h1;
}

// ---------------- launch ----------------
extern "C" void kernel_launch(void* const* d_in, const int* in_sizes, int n_in,
                              void* d_out, int out_size) {
    const float* vf    = (const float*)d_in[0];
    const float* R     = (const float*)d_in[1];
    const float* W_rel = (const float*)d_in[2];
    const float* b_rel = (const float*)d_in[3];
    const float* W_sbj = (const float*)d_in[4];
    const float* b_sbj = (const float*)d_in[5];
    const float* W_obj = (const float*)d_in[6];
    const float* b_obj = (const float*)d_in[7];
    const float* W_ctx = (const float*)d_in[8];
    const float* b_ctx = (const float*)d_in[9];
    const int* sbj     = (const int*)d_in[10];
    const int* obj     = (const int*)d_in[11];
    float* out = (float*)d_out;

    cudaFuncSetAttribute(gemm_multi,   cudaFuncAttributeMaxDynamicSharedMemorySize, SMEM16_BYTES);
    cudaFuncSetAttribute(gemm_logit16, cudaFuncAttributeMaxDynamicSharedMemorySize, SMEM16_BYTES);
    cudaFuncSetAttribute(gemm_vj16,    cudaFuncAttributeMaxDynamicSharedMemorySize, SMEM16_BYTES);

    __half *pHs, *pHo, *pKt, *pMT, *pT, *pWr, *pWT, *pVf;
    cudaGetSymbolAddress((void**)&pHs, g_Hs16);
    cudaGetSymbolAddress((void**)&pHo, g_Ho16);
    cudaGetSymbolAddress((void**)&pKt, g_Kt16);
    cudaGetSymbolAddress((void**)&pMT, g_MT16);
    cudaGetSymbolAddress((void**)&pT,  g_T16);
    cudaGetSymbolAddress((void**)&pWr, g_Wr16);
    cudaGetSymbolAddress((void**)&pWT, g_WT16);
    cudaGetSymbolAddress((void**)&pVf, g_vf16);
    float *pS1, *pS2, *pG, *pC3;
    cudaGetSymbolAddress((void**)&pS1, g_S1);
    cudaGetSymbolAddress((void**)&pS2, g_S2);
    cudaGetSymbolAddress((void**)&pG,  g_G);
    cudaGetSymbolAddress((void**)&pC3, g_c3);

    const __half* hWr_s = pWr + 0 * (size_t)DD * DD;
    const __half* hWr_o = pWr + 1 * (size_t)DD * DD;
    const __half* hWr_r = pWr + 2 * (size_t)DD * DD;
    __half* hWs_rT = pWT + 0 * (size_t)DD * DD;
    __half* hWo_rT = pWT + 1 * (size_t)DD * DD;
    __half* hWctxT = pWT + 2 * (size_t)DD * DD;
    __half* hWs_vT = pWT + 3 * (size_t)DD * DD;
    __half* hWo_vT = pWT + 4 * (size_t)DD * DD;

    const float* Ws_v = W_sbj;
    const float* Ws_r = W_sbj + (size_t)DD * DD;
    const float* Wo_v = W_obj;
    const float* Wo_r = W_obj + (size_t)DD * DD;

    k_copyround<<<EE * DD / 4 / 256, 256>>>(R, out);

    k_init<<<(EE + 255) / 256, 256>>>();
    k_hist<<<(EE + 255) / 256, 256>>>(sbj, obj);
    k_scan<<<1, 768>>>();
    k_scatter<<<(EE + 255) / 256, 256>>>(obj);
    k_vecs1p<<<dim3(4, 8), 256>>>(b_rel, Ws_r, Wo_r);
    k_vecs1r<<<4, 256>>>(b_sbj, b_obj);

    k_roundh<<<(3 * DD * DD / 4 + 255) / 256, 256>>>(W_rel, pWr, 3 * DD * DD / 4);
    k_roundh<<<(NN * DD / 4 + 255) / 256, 256>>>(vf, pVf, NN * DD / 4);
    {
        TBatch tb{};
        tb.p[0] = {Ws_r,  hWs_rT};
        tb.p[1] = {Wo_r,  hWo_rT};
        tb.p[2] = {W_ctx, hWctxT};
        tb.p[3] = {Ws_v,  hWs_vT};
        tb.p[4] = {Wo_v,  hWo_vT};
        k_troundh<<<dim3(32, 32, 5), dim3(32, 8)>>>(tb);
    }

    // L1: Hs, Ho, M1T..M4T
    {
        Batch b{};
        b.d[0] = {hWr_r,  hWs_rT, nullptr, nullptr, nullptr, nullptr, nullptr, pHs,                        DD, DD, DD, 0};
        b.d[1] = {hWr_r,  hWo_rT, nullptr, nullptr, nullptr, nullptr, nullptr, pHo,                        DD, DD, DD, 0};
        b.d[2] = {hWs_rT, hWr_s,  nullptr, nullptr, hWs_vT,  nullptr, nullptr, pMT + 0 * (size_t)DD * DD,  DD, DD, DD, 0};
        b.d[3] = {hWs_rT, hWr_o,  nullptr, nullptr, nullptr, nullptr, nullptr, pMT + 1 * (size_t)DD * DD,  DD, DD, DD, 0};
        b.d[4] = {hWo_rT, hWr_o,  nullptr, nullptr, hWo_vT,  nullptr, nullptr, pMT + 2 * (size_t)DD * DD,  DD, DD, DD, 0};
        b.d[5] = {hWo_rT, hWr_s,  nullptr, nullptr, nullptr, nullptr, nullptr, pMT + 3 * (size_t)DD * DD,  DD, DD, DD, 0};
        gemm_multi<<<dim3(8, 8, 6), 128, SMEM16_BYTES>>>(b);
    }
    // c3 from Hs/Ho (before L3 consumes it)
    k_c3<<<128, 256>>>();
    // L2: T_z (M=768) + Kt
    {
        Batch b{};
        for (int z = 0; z < 4; z++)
            b.d[z] = {pVf, pMT + (size_t)z * DD * DD, nullptr, nullptr, nullptr, nullptr, nullptr,
                      pT + (size_t)z * NN * DD, NN, DD, DD, 0};
        b.d[4] = {pHo, pHs, nullptr, nullptr, nullptr, nullptr, nullptr, pKt, DD, DD, DD, 0};
        gemm_multi<<<dim3(8, 8, 5), 128, SMEM16_BYTES>>>(b);
    }
    // L3: S1 (+c3 row), S2, G
    {
        Batch b{};
        b.d[0] = {pT + 0 * (size_t)NN * DD, pHo, pT + 3 * (size_t)NN * DD, pHs, nullptr, pC3, pS1, nullptr,
                  NN, DD, DD, 1};
        b.d[1] = {pT + 1 * (size_t)NN * DD, pHo, pT + 2 * (size_t)NN * DD, pHs, nullptr, nullptr, pS2, nullptr,
                  NN, DD, DD, 1};
        b.d[2] = {pT + 0 * (size_t)NN * DD, pT + 2 * (size_t)NN * DD,
                  pT + 3 * (size_t)NN * DD, pT + 1 * (size_t)NN * DD, nullptr, nullptr, pG, nullptr,
                  NN, NN, NN, 1};
        gemm_multi<<<dim3(8, 6, 3), 128, SMEM16_BYTES>>>(b);
    }
    k_scal<<<96, 256>>>();

    gemm_logit16<<<dim3(8, 192, 2), 128, SMEM16_BYTES>>>(sbj, obj);

    k_max<<<(EE + 255) / 256, 256>>>(sbj, obj);
    k_exp<<<(EE + 255) / 256, 256>>>(sbj, obj);
    k_ctx<<<NN, 256>>>(sbj, obj, vf);

    gemm_vj16<<<dim3(8, 6), 128, SMEM16_BYTES>>>(hWctxT, b_ctx, vf, out + (size_t)EE * DD);

    (void)in_sizes; (void)n_in; (void)out_size;
}